// round 15
// baseline (speedup 1.0000x reference)
#include <cuda_runtime.h>
#include <cuda_fp16.h>
#include <math.h>
#include <stdint.h>

// Problem constants (fixed by the dataset)
#define BB   4
#define N1   4096
#define N2   16384
#define DIM1 512
#define DIM2 256
#define DOUT 256
#define QS   1024              // sources per KNN quarter
#define NQ   4                 // quarters

// Scratch (no allocation allowed -> __device__ globals)
__device__ float g_feats1[BB * N1 * DOUT];
__device__ int   g_idx[BB * N2 * 3];
__device__ float g_w[BB * N2 * 3];
__device__ float g_pd[BB * N2 * NQ * 3];      // partial top-3 distances
__device__ int   g_pi[BB * N2 * NQ * 3];      // partial top-3 global rows
__device__ __half g_p1[BB * N1 * DIM1];
__device__ __half g_p2[BB * N2 * DIM2];
__device__ __half g_w1[DOUT * DIM1];
__device__ __half g_w2[DOUT * DIM2];

// ---------------------------------------------------------------------------
// Helpers
// ---------------------------------------------------------------------------
__device__ __forceinline__ uint32_t smem_u32(const void* p) {
    return (uint32_t)__cvta_generic_to_shared(p);
}
__device__ __forceinline__ void ldsm4(uint32_t* r, uint32_t a) {
    asm volatile("ldmatrix.sync.aligned.m8n8.x4.shared.b16 {%0,%1,%2,%3}, [%4];\n"
        : "=r"(r[0]), "=r"(r[1]), "=r"(r[2]), "=r"(r[3]) : "r"(a));
}
__device__ __forceinline__ void mma16816(float* d, const uint32_t* a, const uint32_t* b) {
    asm volatile(
        "mma.sync.aligned.m16n8k16.row.col.f32.f16.f16.f32 "
        "{%0,%1,%2,%3},{%4,%5,%6,%7},{%8,%9},{%0,%1,%2,%3};\n"
        : "+f"(d[0]), "+f"(d[1]), "+f"(d[2]), "+f"(d[3])
        : "r"(a[0]), "r"(a[1]), "r"(a[2]), "r"(a[3]), "r"(b[0]), "r"(b[1]));
}
__device__ __forceinline__ uint32_t pack_h2(__half a, __half b) {
    __half2 t; t.x = a; t.y = b;
    return *reinterpret_cast<uint32_t*>(&t);
}
__device__ __forceinline__ void cpasync16(uint32_t dst, const void* src) {
    asm volatile("cp.async.cg.shared.global [%0], [%1], 16;\n"
        :: "r"(dst), "l"(src) : "memory");
}
__device__ __forceinline__ void cp_commit() {
    asm volatile("cp.async.commit_group;\n" ::: "memory");
}
template <int N> __device__ __forceinline__ void cp_wait() {
    asm volatile("cp.async.wait_group %0;\n" :: "n"(N) : "memory");
}

// Swizzled element offset of 8-element (16B) chunk c within row r (32 elems/row)
__device__ __forceinline__ int swz(int r, int c) {
    return r * 32 + ((c ^ ((r >> 1) & 3)) << 3);
}
__device__ __forceinline__ uint32_t addrA(uint32_t base, int row0, int c0, int lane) {
    int g = lane >> 3;
    int r = row0 + (lane & 7) + ((g & 1) << 3);
    int c = c0 + (g >> 1);
    return base + (uint32_t)(swz(r, c) * 2);
}
__device__ __forceinline__ uint32_t addrB(uint32_t base, int row0, int c0, int lane) {
    int g = lane >> 3;
    int r = row0 + (lane & 7) + ((g >> 1) << 3);
    int c = c0 + (g & 1);
    return base + (uint32_t)(swz(r, c) * 2);
}

// ---------------------------------------------------------------------------
// fp32 -> fp16 (single rounding). n4 = count/4.
// ---------------------------------------------------------------------------
__global__ __launch_bounds__(256)
void cvt_f16_kernel(const float* __restrict__ x, __half* __restrict__ h, int n4)
{
    int i = blockIdx.x * 256 + threadIdx.x;
    if (i >= n4) return;
    float4 v = reinterpret_cast<const float4*>(x)[i];
    uint2 o;
    o.x = pack_h2(__float2half_rn(v.x), __float2half_rn(v.y));
    o.y = pack_h2(__float2half_rn(v.z), __float2half_rn(v.w));
    reinterpret_cast<uint2*>(h)[i] = o;
}

// ---------------------------------------------------------------------------
// GEMM (single fp16 operands, mma.sync) + BN(eval) + ReLU — proven R14 kernel.
// Block 128(M) x 128(N) x 64(K); 256 threads = 8 warps (2m x 4n); warp 64x32.
// ---------------------------------------------------------------------------
#define STG 32768
#define GSM_SC (3 * STG)
#define GSM_SH (3 * STG + 1024)
#define GSM_TOTAL (3 * STG + 2048)

__global__ __launch_bounds__(256, 2)
void gemm_mma_bn_relu(const __half* __restrict__ A_g,
                      const __half* __restrict__ W_g,
                      const float* __restrict__ bias,
                      const float* __restrict__ gamma,
                      const float* __restrict__ beta,
                      const float* __restrict__ mean,
                      const float* __restrict__ var,
                      float* __restrict__ C,         // [M,256]
                      int K)
{
    extern __shared__ __align__(16) char smem[];
    float* s_sc = reinterpret_cast<float*>(smem + GSM_SC);
    float* s_sh = reinterpret_cast<float*>(smem + GSM_SH);

    const int tid  = threadIdx.x;
    const int lane = tid & 31;
    const int wid  = tid >> 5;
    const int wm   = wid & 1;
    const int wn   = wid >> 1;
    const int m0   = blockIdx.x * 128;
    const int n0   = blockIdx.y * 128;

    {   // BN fold
        float s = gamma[tid] * rsqrtf(var[tid] + 1e-5f);
        s_sc[tid] = s;
        s_sh[tid] = fmaf(bias[tid] - mean[tid], s, beta[tid]);
    }

    float acc[4][4][4];
#pragma unroll
    for (int i = 0; i < 4; i++)
#pragma unroll
        for (int j = 0; j < 4; j++)
#pragma unroll
            for (int q = 0; q < 4; q++) acc[i][j][q] = 0.f;

    const uint32_t sb = smem_u32(smem);

    auto issue = [&](int it) {
        const int k0 = it * 64;
        const uint32_t base = sb + (it % 3) * STG;
#pragma unroll
        for (int c = tid; c < 1024; c += 256) {
            int sub = c >> 9, cc = c & 511;
            int row = cc >> 2, kc = cc & 3;
            int d = sub * 8192 + swz(row, kc) * 2;
            size_t s = (size_t)(m0 + row) * K + k0 + sub * 32 + kc * 8;
            cpasync16(base + d, A_g + s);
        }
#pragma unroll
        for (int c = tid; c < 1024; c += 256) {
            int sub = c >> 9, cc = c & 511;
            int row = cc >> 2, kc = cc & 3;
            int d = 16384 + sub * 8192 + swz(row, kc) * 2;
            size_t s = (size_t)(n0 + row) * K + k0 + sub * 32 + kc * 8;
            cpasync16(base + d, W_g + s);
        }
    };

    const int T = K / 64;
    issue(0); cp_commit();
    issue(1); cp_commit();

    for (int it = 0; it < T; it++) {
        cp_wait<1>();
        __syncthreads();
        if (it + 2 < T) issue(it + 2);
        cp_commit();

        const uint32_t stage = sb + (it % 3) * STG;
#pragma unroll
        for (int sub = 0; sub < 2; sub++) {
            const uint32_t bA = stage + sub * 8192;
            const uint32_t bB = stage + 16384 + sub * 8192;
#pragma unroll
            for (int kk = 0; kk < 2; kk++) {
                const int c0 = kk * 2;
                uint32_t ah[4][4];
#pragma unroll
                for (int mi = 0; mi < 4; mi++)
                    ldsm4(ah[mi], addrA(bA, wm * 64 + mi * 16, c0, lane));
#pragma unroll
                for (int j = 0; j < 2; j++) {
                    uint32_t bh[4];
                    ldsm4(bh, addrB(bB, wn * 32 + j * 16, c0, lane));
#pragma unroll
                    for (int mi = 0; mi < 4; mi++)
#pragma unroll
                        for (int s = 0; s < 2; s++)
                            mma16816(acc[mi][j * 2 + s], ah[mi], &bh[s * 2]);
                }
            }
        }
    }

    // Epilogue: BN + ReLU
#pragma unroll
    for (int mi = 0; mi < 4; mi++) {
        const int r0 = m0 + wm * 64 + mi * 16 + (lane >> 2);
        const int r1 = r0 + 8;
#pragma unroll
        for (int nf = 0; nf < 4; nf++) {
            const int cc = n0 + wn * 32 + nf * 8 + 2 * (lane & 3);
            const float sc0 = s_sc[cc], sc1 = s_sc[cc + 1];
            const float sh0 = s_sh[cc], sh1 = s_sh[cc + 1];
            float* a = acc[mi][nf];
            float2 o0, o1;
            o0.x = fmaxf(fmaf(a[0], sc0, sh0), 0.f);
            o0.y = fmaxf(fmaf(a[1], sc1, sh1), 0.f);
            o1.x = fmaxf(fmaf(a[2], sc0, sh0), 0.f);
            o1.y = fmaxf(fmaf(a[3], sc1, sh1), 0.f);
            *reinterpret_cast<float2*>(&C[(size_t)r0 * DOUT + cc]) = o0;
            *reinterpret_cast<float2*>(&C[(size_t)r1 * DOUT + cc]) = o1;
        }
    }
}

// ---------------------------------------------------------------------------
// KNN phase A: partial top-3 over one source QUARTER (1024 sources, 16KB
// smem), 4 targets per thread so each broadcast LDS.128 serves 128 pairs.
// Grid (N2/1024, BB, NQ) = 256 blocks, 256 threads.
// Stores raw expanded distances (|s|^2 - 2 t.s) and GLOBAL feats1 rows.
// ---------------------------------------------------------------------------
__global__ __launch_bounds__(256)
void knn3_partial_kernel(const float* __restrict__ xyz_tgt,
                         const float* __restrict__ xyz_src,
                         float* __restrict__ pd,
                         int* __restrict__ pi)
{
    __shared__ float4 sp[QS];                        // 16KB

    const int b  = blockIdx.y;
    const int q  = blockIdx.z;
    const int s0 = q * QS;
    const int t0 = blockIdx.x * 1024 + threadIdx.x;  // + k*256

    const float* src = xyz_src + ((size_t)b * N1 + s0) * 3;
    for (int i = threadIdx.x; i < QS; i += 256) {
        float x = src[3 * i + 0];
        float y = src[3 * i + 1];
        float z = src[3 * i + 2];
        sp[i] = make_float4(x, y, z, x * x + y * y + z * z);
    }
    __syncthreads();

    float mx[4], my[4], mz[4];
    float d0[4], d1[4], d2[4];
    int   i0[4], i1[4], i2[4];
#pragma unroll
    for (int k = 0; k < 4; k++) {
        const float* tp = xyz_tgt + ((size_t)b * N2 + t0 + k * 256) * 3;
        mx[k] = -2.f * tp[0];
        my[k] = -2.f * tp[1];
        mz[k] = -2.f * tp[2];
        d0[k] = 3.4e38f; d1[k] = 3.4e38f; d2[k] = 3.4e38f;
        i0[k] = 0; i1[k] = 0; i2[k] = 0;
    }

#pragma unroll 4
    for (int s = 0; s < QS; s++) {
        float4 p = sp[s];
#pragma unroll
        for (int k = 0; k < 4; k++) {
            float d = fmaf(p.x, mx[k], fmaf(p.y, my[k], fmaf(p.z, mz[k], p.w)));
            if (d < d2[k]) {
                if (d < d1[k]) {
                    d2[k] = d1[k]; i2[k] = i1[k];
                    if (d < d0[k]) { d1[k] = d0[k]; i1[k] = i0[k];
                                     d0[k] = d;     i0[k] = s; }
                    else           { d1[k] = d;     i1[k] = s; }
                } else {
                    d2[k] = d; i2[k] = s;
                }
            }
        }
    }

#pragma unroll
    for (int k = 0; k < 4; k++) {
        size_t o = (((size_t)b * N2 + t0 + k * 256) * NQ + q) * 3;
        pd[o + 0] = d0[k];  pi[o + 0] = b * N1 + s0 + i0[k];
        pd[o + 1] = d1[k];  pi[o + 1] = b * N1 + s0 + i1[k];
        pd[o + 2] = d2[k];  pi[o + 2] = b * N1 + s0 + i2[k];
    }
}

// ---------------------------------------------------------------------------
// KNN phase B: merge NQ*3 candidates per target -> final top-3 + weights.
// Candidates iterated in (quarter, rank) order = ascending source order on
// ties, matching the original single-pass semantics. One thread per target.
// ---------------------------------------------------------------------------
__global__ __launch_bounds__(256)
void knn3_merge_kernel(const float* __restrict__ xyz_tgt,
                       const float* __restrict__ pd,
                       const int* __restrict__ pi,
                       int* __restrict__ idx,
                       float* __restrict__ w)
{
    const int t = blockIdx.x * 256 + threadIdx.x;    // flat target (b*N2+t)
    const float* tp = xyz_tgt + (size_t)t * 3;
    const float t2 = tp[0]*tp[0] + tp[1]*tp[1] + tp[2]*tp[2];

    float d0 = 3.4e38f, d1 = 3.4e38f, d2 = 3.4e38f;
    int   i0 = 0,       i1 = 0,       i2 = 0;

#pragma unroll
    for (int c = 0; c < NQ * 3; c++) {
        float d = pd[(size_t)t * (NQ * 3) + c];
        int   j = pi[(size_t)t * (NQ * 3) + c];
        if (d < d2) {
            if (d < d1) {
                d2 = d1; i2 = i1;
                if (d < d0) { d1 = d0; i1 = i0; d0 = d; i0 = j; }
                else        { d1 = d;  i1 = j; }
            } else {
                d2 = d; i2 = j;
            }
        }
    }

    d0 += t2; d1 += t2; d2 += t2;

    float w0 = 1.f / (d0 + 1e-8f);
    float w1 = 1.f / (d1 + 1e-8f);
    float w2 = 1.f / (d2 + 1e-8f);
    float inv = 1.f / (w0 + w1 + w2);

    idx[t * 3 + 0] = i0;
    idx[t * 3 + 1] = i1;
    idx[t * 3 + 2] = i2;
    w[t * 3 + 0] = w0 * inv;
    w[t * 3 + 1] = w1 * inv;
    w[t * 3 + 2] = w2 * inv;
}

// ---------------------------------------------------------------------------
// out[r,:] += sum_k w[r,k] * feats1[idx[r,k], :]  (out holds feats2 already)
// ---------------------------------------------------------------------------
__global__ __launch_bounds__(256)
void interp_add_kernel(const float* __restrict__ feats1,
                       const int* __restrict__ idx,
                       const float* __restrict__ w,
                       float* __restrict__ out)
{
    const int r  = blockIdx.x * 4 + (threadIdx.x >> 6);
    const int c4 = (threadIdx.x & 63) * 4;

    const int   j0 = idx[r * 3 + 0];
    const int   j1 = idx[r * 3 + 1];
    const int   j2 = idx[r * 3 + 2];
    const float w0 = w[r * 3 + 0];
    const float w1 = w[r * 3 + 1];
    const float w2 = w[r * 3 + 2];

    const float4 f0 = *reinterpret_cast<const float4*>(&feats1[(size_t)j0 * DOUT + c4]);
    const float4 f1 = *reinterpret_cast<const float4*>(&feats1[(size_t)j1 * DOUT + c4]);
    const float4 f2 = *reinterpret_cast<const float4*>(&feats1[(size_t)j2 * DOUT + c4]);

    float4 o = *reinterpret_cast<float4*>(&out[(size_t)r * DOUT + c4]);
    o.x += w0 * f0.x + w1 * f1.x + w2 * f2.x;
    o.y += w0 * f0.y + w1 * f1.y + w2 * f2.y;
    o.z += w0 * f0.z + w1 * f1.z + w2 * f2.z;
    o.w += w0 * f0.w + w1 * f1.w + w2 * f2.w;
    *reinterpret_cast<float4*>(&out[(size_t)r * DOUT + c4]) = o;
}

// ---------------------------------------------------------------------------
extern "C" void kernel_launch(void* const* d_in, const int* in_sizes, int n_in,
                              void* d_out, int out_size)
{
    const float* xyz1    = (const float*)d_in[0];
    const float* points1 = (const float*)d_in[1];
    const float* xyz2    = (const float*)d_in[2];
    const float* points2 = (const float*)d_in[3];
    const float* W1 = (const float*)d_in[4];
    const float* b1 = (const float*)d_in[5];
    const float* g1 = (const float*)d_in[6];
    const float* be1= (const float*)d_in[7];
    const float* m1 = (const float*)d_in[8];
    const float* v1 = (const float*)d_in[9];
    const float* W2 = (const float*)d_in[10];
    const float* b2 = (const float*)d_in[11];
    const float* g2 = (const float*)d_in[12];
    const float* be2= (const float*)d_in[13];
    const float* m2 = (const float*)d_in[14];
    const float* v2 = (const float*)d_in[15];
    float* out = (float*)d_out;

    float* feats1_ptr = nullptr;
    int*   idx_ptr    = nullptr;
    float* w_ptr      = nullptr;
    float* pd_ptr     = nullptr;
    int*   pi_ptr     = nullptr;
    __half *p1, *p2, *w1, *w2;
    cudaGetSymbolAddress((void**)&feats1_ptr, g_feats1);
    cudaGetSymbolAddress((void**)&idx_ptr,    g_idx);
    cudaGetSymbolAddress((void**)&w_ptr,      g_w);
    cudaGetSymbolAddress((void**)&pd_ptr,     g_pd);
    cudaGetSymbolAddress((void**)&pi_ptr,     g_pi);
    cudaGetSymbolAddress((void**)&p1, g_p1);
    cudaGetSymbolAddress((void**)&p2, g_p2);
    cudaGetSymbolAddress((void**)&w1, g_w1);
    cudaGetSymbolAddress((void**)&w2, g_w2);

    // One-time setup (outside capture on the first/correctness call)
    static cudaStream_t sA = nullptr, sB = nullptr;
    static cudaEvent_t evRoot = nullptr, evA = nullptr, evB = nullptr;
    static int attr_set = 0;
    if (!attr_set) {
        cudaFuncSetAttribute(gemm_mma_bn_relu,
                             cudaFuncAttributeMaxDynamicSharedMemorySize,
                             GSM_TOTAL);
        cudaStreamCreateWithFlags(&sA, cudaStreamNonBlocking);
        cudaStreamCreateWithFlags(&sB, cudaStreamNonBlocking);
        cudaEventCreateWithFlags(&evRoot, cudaEventDisableTiming);
        cudaEventCreateWithFlags(&evA, cudaEventDisableTiming);
        cudaEventCreateWithFlags(&evB, cudaEventDisableTiming);
        attr_set = 1;
    }

    // Fork
    cudaEventRecord(evRoot, 0);
    cudaStreamWaitEvent(sA, evRoot, 0);
    cudaStreamWaitEvent(sB, evRoot, 0);

    // sA: KNN phase A (partial top-3 per quarter) then phase B (merge)
    knn3_partial_kernel<<<dim3(N2 / 1024, BB, NQ), 256, 0, sA>>>(
        xyz2, xyz1, pd_ptr, pi_ptr);
    knn3_merge_kernel<<<(BB * N2) / 256, 256, 0, sA>>>(
        xyz2, pd_ptr, pi_ptr, idx_ptr, w_ptr);

    // sB: cvt(points1), cvt(W1), GEMM1 -> feats1
    {
        int n4 = BB * N1 * DIM1 / 4;
        cvt_f16_kernel<<<(n4 + 255) / 256, 256, 0, sB>>>(points1, p1, n4);
        n4 = DOUT * DIM1 / 4;
        cvt_f16_kernel<<<(n4 + 255) / 256, 256, 0, sB>>>(W1, w1, n4);
        gemm_mma_bn_relu<<<dim3((BB * N1) / 128, 2), 256, GSM_TOTAL, sB>>>(
            p1, w1, b1, g1, be1, m1, v1, feats1_ptr, DIM1);
    }

    // stream 0: cvt(points2), cvt(W2), GEMM2-pure -> out
    {
        int n4 = BB * N2 * DIM2 / 4;
        cvt_f16_kernel<<<(n4 + 255) / 256, 256>>>(points2, p2, n4);
        n4 = DOUT * DIM2 / 4;
        cvt_f16_kernel<<<(n4 + 255) / 256, 256>>>(W2, w2, n4);
        gemm_mma_bn_relu<<<dim3((BB * N2) / 128, 2), 256, GSM_TOTAL>>>(
            p2, w2, b2, g2, be2, m2, v2, out, DIM2);
    }

    // Join: interp_add needs KNN (sA), GEMM1 (sB), GEMM2 (stream 0)
    cudaEventRecord(evA, sA);
    cudaEventRecord(evB, sB);
    cudaStreamWaitEvent(0, evA, 0);
    cudaStreamWaitEvent(0, evB, 0);

    // out += 3-NN weighted interpolation of feats1
    interp_add_kernel<<<(BB * N2) / 4, 256>>>(feats1_ptr, idx_ptr, w_ptr, out);
}

// round 16
// speedup vs baseline: 1.2525x; 1.2525x over previous
#include <cuda_runtime.h>
#include <cuda_fp16.h>
#include <math.h>
#include <stdint.h>

// Problem constants (fixed by the dataset)
#define BB   4
#define N1   4096
#define N2   16384
#define DIM1 512
#define DIM2 256
#define DOUT 256

// Scratch (no allocation allowed -> __device__ globals)
__device__ float g_feats1[BB * N1 * DOUT];
__device__ int   g_idx[BB * N2 * 3];
__device__ float g_w[BB * N2 * 3];
__device__ __half g_p1[BB * N1 * DIM1];
__device__ __half g_p2[BB * N2 * DIM2];
__device__ __half g_w1[DOUT * DIM1];
__device__ __half g_w2[DOUT * DIM2];

// ---------------------------------------------------------------------------
// Helpers
// ---------------------------------------------------------------------------
__device__ __forceinline__ uint32_t smem_u32(const void* p) {
    return (uint32_t)__cvta_generic_to_shared(p);
}
__device__ __forceinline__ void ldsm4(uint32_t* r, uint32_t a) {
    asm volatile("ldmatrix.sync.aligned.m8n8.x4.shared.b16 {%0,%1,%2,%3}, [%4];\n"
        : "=r"(r[0]), "=r"(r[1]), "=r"(r[2]), "=r"(r[3]) : "r"(a));
}
__device__ __forceinline__ void mma16816(float* d, const uint32_t* a, const uint32_t* b) {
    asm volatile(
        "mma.sync.aligned.m16n8k16.row.col.f32.f16.f16.f32 "
        "{%0,%1,%2,%3},{%4,%5,%6,%7},{%8,%9},{%0,%1,%2,%3};\n"
        : "+f"(d[0]), "+f"(d[1]), "+f"(d[2]), "+f"(d[3])
        : "r"(a[0]), "r"(a[1]), "r"(a[2]), "r"(a[3]), "r"(b[0]), "r"(b[1]));
}
__device__ __forceinline__ uint32_t pack_h2(__half a, __half b) {
    __half2 t; t.x = a; t.y = b;
    return *reinterpret_cast<uint32_t*>(&t);
}
__device__ __forceinline__ void cpasync16(uint32_t dst, const void* src) {
    asm volatile("cp.async.cg.shared.global [%0], [%1], 16;\n"
        :: "r"(dst), "l"(src) : "memory");
}
__device__ __forceinline__ void cp_commit() {
    asm volatile("cp.async.commit_group;\n" ::: "memory");
}
template <int N> __device__ __forceinline__ void cp_wait() {
    asm volatile("cp.async.wait_group %0;\n" :: "n"(N) : "memory");
}

// Swizzled element offset of 8-element (16B) chunk c within row r (32 elems/row)
__device__ __forceinline__ int swz(int r, int c) {
    return r * 32 + ((c ^ ((r >> 1) & 3)) << 3);
}
__device__ __forceinline__ uint32_t addrA(uint32_t base, int row0, int c0, int lane) {
    int g = lane >> 3;
    int r = row0 + (lane & 7) + ((g & 1) << 3);
    int c = c0 + (g >> 1);
    return base + (uint32_t)(swz(r, c) * 2);
}
__device__ __forceinline__ uint32_t addrB(uint32_t base, int row0, int c0, int lane) {
    int g = lane >> 3;
    int r = row0 + (lane & 7) + ((g >> 1) << 3);
    int c = c0 + (g & 1);
    return base + (uint32_t)(swz(r, c) * 2);
}

// ---------------------------------------------------------------------------
// fp32 -> fp16 (single rounding). n4 = count/4.
// ---------------------------------------------------------------------------
__global__ __launch_bounds__(256)
void cvt_f16_kernel(const float* __restrict__ x, __half* __restrict__ h, int n4)
{
    int i = blockIdx.x * 256 + threadIdx.x;
    if (i >= n4) return;
    float4 v = reinterpret_cast<const float4*>(x)[i];
    uint2 o;
    o.x = pack_h2(__float2half_rn(v.x), __float2half_rn(v.y));
    o.y = pack_h2(__float2half_rn(v.z), __float2half_rn(v.w));
    reinterpret_cast<uint2*>(h)[i] = o;
}

// ---------------------------------------------------------------------------
// GEMM (single fp16 operands, mma.sync) + BN(eval) + ReLU — proven R14 kernel.
// Block 128(M) x 128(N) x 64(K); 256 threads = 8 warps (2m x 4n); warp 64x32.
// ---------------------------------------------------------------------------
#define STG 32768
#define GSM_SC (3 * STG)
#define GSM_SH (3 * STG + 1024)
#define GSM_TOTAL (3 * STG + 2048)

__global__ __launch_bounds__(256, 2)
void gemm_mma_bn_relu(const __half* __restrict__ A_g,
                      const __half* __restrict__ W_g,
                      const float* __restrict__ bias,
                      const float* __restrict__ gamma,
                      const float* __restrict__ beta,
                      const float* __restrict__ mean,
                      const float* __restrict__ var,
                      float* __restrict__ C,         // [M,256]
                      int K)
{
    extern __shared__ __align__(16) char smem[];
    float* s_sc = reinterpret_cast<float*>(smem + GSM_SC);
    float* s_sh = reinterpret_cast<float*>(smem + GSM_SH);

    const int tid  = threadIdx.x;
    const int lane = tid & 31;
    const int wid  = tid >> 5;
    const int wm   = wid & 1;
    const int wn   = wid >> 1;
    const int m0   = blockIdx.x * 128;
    const int n0   = blockIdx.y * 128;

    {   // BN fold
        float s = gamma[tid] * rsqrtf(var[tid] + 1e-5f);
        s_sc[tid] = s;
        s_sh[tid] = fmaf(bias[tid] - mean[tid], s, beta[tid]);
    }

    float acc[4][4][4];
#pragma unroll
    for (int i = 0; i < 4; i++)
#pragma unroll
        for (int j = 0; j < 4; j++)
#pragma unroll
            for (int q = 0; q < 4; q++) acc[i][j][q] = 0.f;

    const uint32_t sb = smem_u32(smem);

    auto issue = [&](int it) {
        const int k0 = it * 64;
        const uint32_t base = sb + (it % 3) * STG;
#pragma unroll
        for (int c = tid; c < 1024; c += 256) {
            int sub = c >> 9, cc = c & 511;
            int row = cc >> 2, kc = cc & 3;
            int d = sub * 8192 + swz(row, kc) * 2;
            size_t s = (size_t)(m0 + row) * K + k0 + sub * 32 + kc * 8;
            cpasync16(base + d, A_g + s);
        }
#pragma unroll
        for (int c = tid; c < 1024; c += 256) {
            int sub = c >> 9, cc = c & 511;
            int row = cc >> 2, kc = cc & 3;
            int d = 16384 + sub * 8192 + swz(row, kc) * 2;
            size_t s = (size_t)(n0 + row) * K + k0 + sub * 32 + kc * 8;
            cpasync16(base + d, W_g + s);
        }
    };

    const int T = K / 64;
    issue(0); cp_commit();
    issue(1); cp_commit();

    for (int it = 0; it < T; it++) {
        cp_wait<1>();
        __syncthreads();
        if (it + 2 < T) issue(it + 2);
        cp_commit();

        const uint32_t stage = sb + (it % 3) * STG;
#pragma unroll
        for (int sub = 0; sub < 2; sub++) {
            const uint32_t bA = stage + sub * 8192;
            const uint32_t bB = stage + 16384 + sub * 8192;
#pragma unroll
            for (int kk = 0; kk < 2; kk++) {
                const int c0 = kk * 2;
                uint32_t ah[4][4];
#pragma unroll
                for (int mi = 0; mi < 4; mi++)
                    ldsm4(ah[mi], addrA(bA, wm * 64 + mi * 16, c0, lane));
#pragma unroll
                for (int j = 0; j < 2; j++) {
                    uint32_t bh[4];
                    ldsm4(bh, addrB(bB, wn * 32 + j * 16, c0, lane));
#pragma unroll
                    for (int mi = 0; mi < 4; mi++)
#pragma unroll
                        for (int s = 0; s < 2; s++)
                            mma16816(acc[mi][j * 2 + s], ah[mi], &bh[s * 2]);
                }
            }
        }
    }

    // Epilogue: BN + ReLU
#pragma unroll
    for (int mi = 0; mi < 4; mi++) {
        const int r0 = m0 + wm * 64 + mi * 16 + (lane >> 2);
        const int r1 = r0 + 8;
#pragma unroll
        for (int nf = 0; nf < 4; nf++) {
            const int cc = n0 + wn * 32 + nf * 8 + 2 * (lane & 3);
            const float sc0 = s_sc[cc], sc1 = s_sc[cc + 1];
            const float sh0 = s_sh[cc], sh1 = s_sh[cc + 1];
            float* a = acc[mi][nf];
            float2 o0, o1;
            o0.x = fmaxf(fmaf(a[0], sc0, sh0), 0.f);
            o0.y = fmaxf(fmaf(a[1], sc1, sh1), 0.f);
            o1.x = fmaxf(fmaf(a[2], sc0, sh0), 0.f);
            o1.y = fmaxf(fmaf(a[3], sc1, sh1), 0.f);
            *reinterpret_cast<float2*>(&C[(size_t)r0 * DOUT + cc]) = o0;
            *reinterpret_cast<float2*>(&C[(size_t)r1 * DOUT + cc]) = o1;
        }
    }
}

// ---------------------------------------------------------------------------
// 3-NN search — 1 target/thread (proven structure) with warp-uniform vote
// gating: 4 distances per iteration; the insert block only runs when some
// lane's min-of-4 beats its current 3rd-best. Inserts execute in ascending
// source order with strict '<', so selection is bit-identical to R14.
// ---------------------------------------------------------------------------
__global__ __launch_bounds__(256)
void knn3_kernel(const float* __restrict__ xyz_tgt,
                 const float* __restrict__ xyz_src,
                 int* __restrict__ idx,
                 float* __restrict__ w)
{
    extern __shared__ float4 sp[];                   // N1 float4 = 64KB

    const int b = blockIdx.y;
    const int t = blockIdx.x * 256 + threadIdx.x;

    const float* src = xyz_src + (size_t)b * N1 * 3;
    for (int i = threadIdx.x; i < N1; i += 256) {
        float x = src[3 * i + 0];
        float y = src[3 * i + 1];
        float z = src[3 * i + 2];
        sp[i] = make_float4(x, y, z, x * x + y * y + z * z);
    }
    __syncthreads();

    const float* tp = xyz_tgt + ((size_t)b * N2 + t) * 3;
    const float tx = tp[0], ty = tp[1], tz = tp[2];
    const float mx = -2.f * tx, my = -2.f * ty, mz = -2.f * tz;
    const float t2 = tx * tx + ty * ty + tz * tz;

    float d0 = 3.4e38f, d1 = 3.4e38f, d2 = 3.4e38f;
    int   i0 = 0,       i1 = 0,       i2 = 0;

#pragma unroll 2
    for (int s = 0; s < N1; s += 4) {
        float dd[4];
#pragma unroll
        for (int j = 0; j < 4; j++) {
            float4 p = sp[s + j];
            dd[j] = fmaf(p.x, mx, fmaf(p.y, my, fmaf(p.z, mz, p.w)));
        }
        float m = fminf(fminf(dd[0], dd[1]), fminf(dd[2], dd[3]));
        if (__any_sync(0xffffffffu, m < d2)) {
#pragma unroll
            for (int j = 0; j < 4; j++) {
                float d = dd[j];
                if (d < d2) {
                    if (d < d1) {
                        d2 = d1; i2 = i1;
                        if (d < d0) { d1 = d0; i1 = i0; d0 = d; i0 = s + j; }
                        else        { d1 = d;  i1 = s + j; }
                    } else {
                        d2 = d; i2 = s + j;
                    }
                }
            }
        }
    }

    d0 += t2; d1 += t2; d2 += t2;

    float w0 = 1.f / (d0 + 1e-8f);
    float w1 = 1.f / (d1 + 1e-8f);
    float w2 = 1.f / (d2 + 1e-8f);
    float inv = 1.f / (w0 + w1 + w2);

    size_t o = ((size_t)b * N2 + t) * 3;
    idx[o + 0] = b * N1 + i0;
    idx[o + 1] = b * N1 + i1;
    idx[o + 2] = b * N1 + i2;
    w[o + 0] = w0 * inv;
    w[o + 1] = w1 * inv;
    w[o + 2] = w2 * inv;
}

// ---------------------------------------------------------------------------
// out[r,:] += sum_k w[r,k] * feats1[idx[r,k], :]  (out holds feats2 already)
// ---------------------------------------------------------------------------
__global__ __launch_bounds__(256)
void interp_add_kernel(const float* __restrict__ feats1,
                       const int* __restrict__ idx,
                       const float* __restrict__ w,
                       float* __restrict__ out)
{
    const int r  = blockIdx.x * 4 + (threadIdx.x >> 6);
    const int c4 = (threadIdx.x & 63) * 4;

    const int   j0 = idx[r * 3 + 0];
    const int   j1 = idx[r * 3 + 1];
    const int   j2 = idx[r * 3 + 2];
    const float w0 = w[r * 3 + 0];
    const float w1 = w[r * 3 + 1];
    const float w2 = w[r * 3 + 2];

    const float4 f0 = *reinterpret_cast<const float4*>(&feats1[(size_t)j0 * DOUT + c4]);
    const float4 f1 = *reinterpret_cast<const float4*>(&feats1[(size_t)j1 * DOUT + c4]);
    const float4 f2 = *reinterpret_cast<const float4*>(&feats1[(size_t)j2 * DOUT + c4]);

    float4 o = *reinterpret_cast<float4*>(&out[(size_t)r * DOUT + c4]);
    o.x += w0 * f0.x + w1 * f1.x + w2 * f2.x;
    o.y += w0 * f0.y + w1 * f1.y + w2 * f2.y;
    o.z += w0 * f0.z + w1 * f1.z + w2 * f2.z;
    o.w += w0 * f0.w + w1 * f1.w + w2 * f2.w;
    *reinterpret_cast<float4*>(&out[(size_t)r * DOUT + c4]) = o;
}

// ---------------------------------------------------------------------------
extern "C" void kernel_launch(void* const* d_in, const int* in_sizes, int n_in,
                              void* d_out, int out_size)
{
    const float* xyz1    = (const float*)d_in[0];
    const float* points1 = (const float*)d_in[1];
    const float* xyz2    = (const float*)d_in[2];
    const float* points2 = (const float*)d_in[3];
    const float* W1 = (const float*)d_in[4];
    const float* b1 = (const float*)d_in[5];
    const float* g1 = (const float*)d_in[6];
    const float* be1= (const float*)d_in[7];
    const float* m1 = (const float*)d_in[8];
    const float* v1 = (const float*)d_in[9];
    const float* W2 = (const float*)d_in[10];
    const float* b2 = (const float*)d_in[11];
    const float* g2 = (const float*)d_in[12];
    const float* be2= (const float*)d_in[13];
    const float* m2 = (const float*)d_in[14];
    const float* v2 = (const float*)d_in[15];
    float* out = (float*)d_out;

    float* feats1_ptr = nullptr;
    int*   idx_ptr    = nullptr;
    float* w_ptr      = nullptr;
    __half *p1, *p2, *w1, *w2;
    cudaGetSymbolAddress((void**)&feats1_ptr, g_feats1);
    cudaGetSymbolAddress((void**)&idx_ptr,    g_idx);
    cudaGetSymbolAddress((void**)&w_ptr,      g_w);
    cudaGetSymbolAddress((void**)&p1, g_p1);
    cudaGetSymbolAddress((void**)&p2, g_p2);
    cudaGetSymbolAddress((void**)&w1, g_w1);
    cudaGetSymbolAddress((void**)&w2, g_w2);

    // One-time setup (outside capture on the first/correctness call)
    static cudaStream_t sA = nullptr, sB = nullptr;
    static cudaEvent_t evRoot = nullptr, evA = nullptr, evB = nullptr;
    static int attr_set = 0;
    if (!attr_set) {
        cudaFuncSetAttribute(knn3_kernel,
                             cudaFuncAttributeMaxDynamicSharedMemorySize,
                             N1 * (int)sizeof(float4));
        cudaFuncSetAttribute(gemm_mma_bn_relu,
                             cudaFuncAttributeMaxDynamicSharedMemorySize,
                             GSM_TOTAL);
        cudaStreamCreateWithFlags(&sA, cudaStreamNonBlocking);
        cudaStreamCreateWithFlags(&sB, cudaStreamNonBlocking);
        cudaEventCreateWithFlags(&evRoot, cudaEventDisableTiming);
        cudaEventCreateWithFlags(&evA, cudaEventDisableTiming);
        cudaEventCreateWithFlags(&evB, cudaEventDisableTiming);
        attr_set = 1;
    }

    // Fork
    cudaEventRecord(evRoot, 0);
    cudaStreamWaitEvent(sA, evRoot, 0);
    cudaStreamWaitEvent(sB, evRoot, 0);

    // sA: KNN (independent of everything else)
    knn3_kernel<<<dim3(N2 / 256, BB), 256, N1 * sizeof(float4), sA>>>(
        xyz2, xyz1, idx_ptr, w_ptr);

    // sB: cvt(points1), cvt(W1), GEMM1 -> feats1
    {
        int n4 = BB * N1 * DIM1 / 4;
        cvt_f16_kernel<<<(n4 + 255) / 256, 256, 0, sB>>>(points1, p1, n4);
        n4 = DOUT * DIM1 / 4;
        cvt_f16_kernel<<<(n4 + 255) / 256, 256, 0, sB>>>(W1, w1, n4);
        gemm_mma_bn_relu<<<dim3((BB * N1) / 128, 2), 256, GSM_TOTAL, sB>>>(
            p1, w1, b1, g1, be1, m1, v1, feats1_ptr, DIM1);
    }

    // stream 0: cvt(points2), cvt(W2), GEMM2-pure -> out
    {
        int n4 = BB * N2 * DIM2 / 4;
        cvt_f16_kernel<<<(n4 + 255) / 256, 256>>>(points2, p2, n4);
        n4 = DOUT * DIM2 / 4;
        cvt_f16_kernel<<<(n4 + 255) / 256, 256>>>(W2, w2, n4);
        gemm_mma_bn_relu<<<dim3((BB * N2) / 128, 2), 256, GSM_TOTAL>>>(
            p2, w2, b2, g2, be2, m2, v2, out, DIM2);
    }

    // Join: interp_add needs KNN (sA), GEMM1 (sB), GEMM2 (stream 0)
    cudaEventRecord(evA, sA);
    cudaEventRecord(evB, sB);
    cudaStreamWaitEvent(0, evA, 0);
    cudaStreamWaitEvent(0, evB, 0);

    // out += 3-NN weighted interpolation of feats1
    interp_add_kernel<<<(BB * N2) / 4, 256>>>(feats1_ptr, idx_ptr, w_ptr, out);
}